// round 8
// baseline (speedup 1.0000x reference)
#include <cuda_runtime.h>
#include <cuda_bf16.h>
#include <cstdint>

#define NN   50000
#define FIN  336
#define HC   512
#define NH   4
#define CH   128
#define NE   500000
#define NEP  (NE + NN)
#define MPAD 50048            // 391 * 128
#define KP1  384
#define KP2  512
#define NBLK 196              // ceil(NN/256)

// ---------------- scratch (device globals; no allocation allowed) ----------
__device__ __align__(16) float g_h[(size_t)NN * HC];
__device__ __align__(16) float g_out[(size_t)NN * HC];
__device__ __align__(16) float g_z[(size_t)NN * CH];
__device__ __align__(16) float g_asrc[NN * NH];
__device__ __align__(16) float g_adst[NN * NH];
__device__ int g_src[NEP];
__device__ int g_dst[NEP];
__device__ int g_csr[NEP];
__device__ int g_deg[NN];
__device__ int g_scan[NN];
__device__ int g_bsum[256];
__device__ int g_rowptr[NN + 1];
__device__ int g_cursor[NN];
__device__ int g_is64;

__device__ __align__(16) __nv_bfloat16 g_ahi[(size_t)MPAD * KP2];
__device__ __align__(16) __nv_bfloat16 g_alo[(size_t)MPAD * KP2];
__device__ __align__(16) __nv_bfloat16 g_bhi[(size_t)HC * KP2];
__device__ __align__(16) __nv_bfloat16 g_blo[(size_t)HC * KP2];

// ---------------- helpers ---------------------------------------------------
__device__ __forceinline__ uint32_t smem_u32(const void* p) {
    uint32_t a;
    asm("{ .reg .u64 t; cvta.to.shared.u64 t, %1; cvt.u32.u64 %0, t; }" : "=r"(a) : "l"(p));
    return a;
}
__device__ __forceinline__ void cp16(uint32_t saddr, const void* g) {
    asm volatile("cp.async.cg.shared.global [%0], [%1], 16;" :: "r"(saddr), "l"(g));
}
#define CP_COMMIT()  asm volatile("cp.async.commit_group;" ::: "memory")
#define CP_WAIT(n)   asm volatile("cp.async.wait_group %0;" :: "n"(n) : "memory")

#define LDMX4(r0, r1, r2, r3, addr)                                            \
    asm volatile("ldmatrix.sync.aligned.m8n8.x4.shared.b16 {%0,%1,%2,%3}, [%4];" \
                 : "=r"(r0), "=r"(r1), "=r"(r2), "=r"(r3) : "r"(addr))

#define MMA16816(c, a, b0, b1)                                                 \
    asm volatile("mma.sync.aligned.m16n8k16.row.col.f32.bf16.bf16.f32 "        \
                 "{%0,%1,%2,%3}, {%4,%5,%6,%7}, {%8,%9}, {%0,%1,%2,%3};"       \
                 : "+f"((c)[0]), "+f"((c)[1]), "+f"((c)[2]), "+f"((c)[3])      \
                 : "r"((a)[0]), "r"((a)[1]), "r"((a)[2]), "r"((a)[3]),         \
                   "r"(b0), "r"(b1))

// ---------------- split-bf16 conversions ------------------------------------
__global__ void conv_a(const float* __restrict__ src, int Kin, int Kpad) {
    const int idx = blockIdx.x * blockDim.x + threadIdx.x;
    const int qpr = Kpad >> 2;
    if (idx >= MPAD * qpr) return;
    const int row = idx / qpr, col = (idx - row * qpr) << 2;
    float4 v = make_float4(0.f, 0.f, 0.f, 0.f);
    if (row < NN && col < Kin)
        v = *(const float4*)(src + (size_t)row * Kin + col);
    __nv_bfloat162 h01 = __floats2bfloat162_rn(v.x, v.y);
    __nv_bfloat162 h23 = __floats2bfloat162_rn(v.z, v.w);
    __nv_bfloat162 l01 = __floats2bfloat162_rn(v.x - __bfloat162float(h01.x),
                                               v.y - __bfloat162float(h01.y));
    __nv_bfloat162 l23 = __floats2bfloat162_rn(v.z - __bfloat162float(h23.x),
                                               v.w - __bfloat162float(h23.y));
    *(uint2*)(g_ahi + (size_t)idx * 4) = make_uint2(*(uint32_t*)&h01, *(uint32_t*)&h23);
    *(uint2*)(g_alo + (size_t)idx * 4) = make_uint2(*(uint32_t*)&l01, *(uint32_t*)&l23);
}

__global__ void conv_w(const float* __restrict__ W, int K, int N, int Kpad) {
    int idx = blockIdx.x * blockDim.x + threadIdx.x;
    if (idx >= N * Kpad) return;
    int n = idx / Kpad, k = idx - n * Kpad;
    float v = (k < K) ? W[(size_t)k * N + n] : 0.f;
    __nv_bfloat16 h = __float2bfloat16(v);
    g_bhi[idx] = h;
    g_blo[idx] = __float2bfloat16(v - __bfloat162float(h));
}

// ---------------- pipelined mma.sync GEMM: C = A[M,K] @ Bt[N,K]^T -----------
// CTA tile 128x128, BK=32, 8 warps (2M x 4N, warp 64x32), 2-stage cp.async.
#define APITCH 40                     // halves per smem row
#define PLANE  (128 * APITCH * 2)     // 10240 B per plane tile
#define STAGEB (4 * PLANE)            // Ahi|Alo|Bhi|Blo = 40960 B
template <int ACT>
__global__ void __launch_bounds__(256, 1) gemm_mma(
    const __nv_bfloat16* __restrict__ Ahi, const __nv_bfloat16* __restrict__ Alo,
    const __nv_bfloat16* __restrict__ Bhi, const __nv_bfloat16* __restrict__ Blo,
    float* __restrict__ C, int Kpad, int ldc, const float* __restrict__ bias) {
    extern __shared__ __align__(16) char smem[];
    const uint32_t sb0 = smem_u32(smem);

    const int tid = threadIdx.x, lane = tid & 31, wid = tid >> 5;
    const int wm = wid & 1, wn = wid >> 1;          // warp tile 64(M) x 32(N)
    const int n0 = blockIdx.x * 128, m0 = blockIdx.y * 128;

    // per-thread cp.async chunk coords (2 chunks of 16B per plane)
    const int r0c = tid >> 1, c0c = (tid & 1) << 1; // chunks 0..3, pairs
    // ldmatrix base byte offsets within a plane
    const uint32_t aoff = ((wm * 64 + (lane & 15)) * APITCH + (lane >> 4) * 8) * 2;
    const uint32_t boff = ((wn * 32 + (lane & 7) + (lane >> 4) * 8) * APITCH
                          + ((lane >> 3) & 1) * 8) * 2;

    const int nk = Kpad >> 5;
    float acc[4][4][4] = {};

    // ---- stage loader ----
    auto load_stage = [&](int i, int s) {
        const int k0 = i << 5;
        const uint32_t sb = sb0 + s * STAGEB;
        const __nv_bfloat16* aH = Ahi + (size_t)m0 * Kpad + k0;
        const __nv_bfloat16* aL = Alo + (size_t)m0 * Kpad + k0;
        const __nv_bfloat16* bH = Bhi + (size_t)n0 * Kpad + k0;
        const __nv_bfloat16* bL = Blo + (size_t)n0 * Kpad + k0;
#pragma unroll
        for (int j = 0; j < 2; j++) {
            const int r = r0c, c = c0c + j;         // row 0..127, chunk 0..3
            const uint32_t so = (r * APITCH + c * 8) * 2;
            const size_t go = (size_t)r * Kpad + c * 8;
            cp16(sb + so,             aH + go);
            cp16(sb + PLANE + so,     aL + go);
            cp16(sb + 2 * PLANE + so, bH + go);
            cp16(sb + 3 * PLANE + so, bL + go);
        }
    };

    load_stage(0, 0);
    CP_COMMIT();

    for (int i = 0; i < nk; i++) {
        if (i + 1 < nk) { load_stage(i + 1, (i + 1) & 1); CP_COMMIT(); CP_WAIT(1); }
        else            { CP_WAIT(0); }
        __syncthreads();

        const uint32_t sb = sb0 + (i & 1) * STAGEB;
#pragma unroll
        for (int ks = 0; ks < 2; ks++) {
            const uint32_t kb = ks * 32;            // 16 halves
            uint32_t ah[4][4], al[4][4], bh[2][4], bl[2][4];
#pragma unroll
            for (int mi = 0; mi < 4; mi++) {
                const uint32_t ad = sb + aoff + mi * (16 * APITCH * 2) + kb;
                LDMX4(ah[mi][0], ah[mi][1], ah[mi][2], ah[mi][3], ad);
                LDMX4(al[mi][0], al[mi][1], al[mi][2], al[mi][3], ad + PLANE);
            }
#pragma unroll
            for (int g = 0; g < 2; g++) {
                const uint32_t bd = sb + 2 * PLANE + boff + g * (16 * APITCH * 2) + kb;
                LDMX4(bh[g][0], bh[g][1], bh[g][2], bh[g][3], bd);
                LDMX4(bl[g][0], bl[g][1], bl[g][2], bl[g][3], bd + PLANE);
            }
#pragma unroll
            for (int mi = 0; mi < 4; mi++)
#pragma unroll
                for (int ni = 0; ni < 4; ni++) {
                    const int g = ni >> 1, p = (ni & 1) * 2;
                    MMA16816(acc[mi][ni], ah[mi], bh[g][p], bh[g][p + 1]);
                    MMA16816(acc[mi][ni], ah[mi], bl[g][p], bl[g][p + 1]);
                    MMA16816(acc[mi][ni], al[mi], bh[g][p], bh[g][p + 1]);
                }
        }
        __syncthreads();
    }

    // ---- epilogue ----
#pragma unroll
    for (int mi = 0; mi < 4; mi++) {
        const int ra = m0 + wm * 64 + mi * 16 + (lane >> 2);
        const int rb = ra + 8;
#pragma unroll
        for (int ni = 0; ni < 4; ni++) {
            const int c = n0 + wn * 32 + ni * 8 + (lane & 3) * 2;
            float2 v0 = make_float2(acc[mi][ni][0], acc[mi][ni][1]);
            float2 v1 = make_float2(acc[mi][ni][2], acc[mi][ni][3]);
            if (ACT == 1) {
                const float b0 = bias[c], b1 = bias[c + 1];
                v0.x = fmaxf(v0.x + b0, 0.f); v0.y = fmaxf(v0.y + b1, 0.f);
                v1.x = fmaxf(v1.x + b0, 0.f); v1.y = fmaxf(v1.y + b1, 0.f);
            }
            if (ra < NN) *(float2*)(C + (size_t)ra * ldc + c) = v0;
            if (rb < NN) *(float2*)(C + (size_t)rb * ldc + c) = v1;
        }
    }
}

// ---------------- edge-index probe / convert / CSR build -------------------
__global__ void probe_kernel(const void* __restrict__ ei) {
    const long long* p = (const long long*)ei;
    int ok64 = 1;
    for (int i = 0; i < 64; i++) {
        long long v = p[i];
        if (v < 0 || v >= NN) ok64 = 0;
    }
    g_is64 = ok64;
}

__global__ void zero_deg() {
    const int i = blockIdx.x * blockDim.x + threadIdx.x;
    if (i < NN) g_deg[i] = 0;
}

__global__ void convert_kernel(const void* __restrict__ ei) {
    const int i = blockIdx.x * blockDim.x + threadIdx.x;
    if (i >= NEP) return;
    int s, d;
    if (i < NE) {
        if (g_is64) {
            const long long* p = (const long long*)ei;
            s = (int)p[i]; d = (int)p[NE + i];
        } else {
            const int* p = (const int*)ei;
            s = p[i]; d = p[NE + i];
        }
    } else {
        s = d = i - NE;
    }
    g_src[i] = s;
    g_dst[i] = d;
    atomicAdd(&g_deg[d], 1);
}

__global__ void scan1() {
    __shared__ int sd[256];
    const int b = blockIdx.x, t = threadIdx.x, i = b * 256 + t;
    int v = (i < NN) ? g_deg[i] : 0;
    sd[t] = v;
    __syncthreads();
#pragma unroll
    for (int o = 1; o < 256; o <<= 1) {
        int x = (t >= o) ? sd[t - o] : 0;
        __syncthreads();
        sd[t] += x;
        __syncthreads();
    }
    if (i < NN) g_scan[i] = sd[t];
    if (t == 255) g_bsum[b] = sd[255];
}

__global__ void scan2() {
    __shared__ int sd[256];
    const int t = threadIdx.x;
    sd[t] = (t < NBLK) ? g_bsum[t] : 0;
    __syncthreads();
#pragma unroll
    for (int o = 1; o < 256; o <<= 1) {
        int x = (t >= o) ? sd[t - o] : 0;
        __syncthreads();
        sd[t] += x;
        __syncthreads();
    }
    if (t < NBLK) g_bsum[t] = sd[t];
}

__global__ void scan3() {
    const int i = blockIdx.x * blockDim.x + threadIdx.x;
    if (i >= NN) return;
    const int b = i >> 8;
    const int incl = g_scan[i] + (b > 0 ? g_bsum[b - 1] : 0);
    g_rowptr[i + 1] = incl;
    g_cursor[i] = incl - g_deg[i];
    if (i == 0) g_rowptr[0] = 0;
}

__global__ void csr_scatter() {
    const int e = blockIdx.x * blockDim.x + threadIdx.x;
    if (e >= NEP) return;
    const int pos = atomicAdd(&g_cursor[g_dst[e]], 1);
    g_csr[pos] = g_src[e];
}

// ---------------- alpha coefficients ----------------------------------------
__global__ void alpha_kernel(const float* __restrict__ asrc,
                             const float* __restrict__ adst) {
    const int w = (blockIdx.x * blockDim.x + threadIdx.x) >> 5;
    const int lane = threadIdx.x & 31;
    if (w >= NN * NH) return;
    const int n = w >> 2, hd = w & 3;
    const float4 hv = *(const float4*)(g_h + (size_t)n * HC + hd * CH + lane * 4);
    const float4 as = *(const float4*)(asrc + hd * CH + lane * 4);
    const float4 ad = *(const float4*)(adst + hd * CH + lane * 4);
    float ss = hv.x * as.x + hv.y * as.y + hv.z * as.z + hv.w * as.w;
    float sd = hv.x * ad.x + hv.y * ad.y + hv.z * ad.z + hv.w * ad.w;
#pragma unroll
    for (int o = 16; o > 0; o >>= 1) {
        ss += __shfl_xor_sync(0xffffffffu, ss, o);
        sd += __shfl_xor_sync(0xffffffffu, sd, o);
    }
    if (lane == 0) { g_asrc[w] = ss; g_adst[w] = sd; }
}

// ---------------- fused gather aggregation (online softmax) ----------------
template <int DO_ELU>
__global__ void __launch_bounds__(128) agg_kernel(const float* __restrict__ bias) {
    __shared__ __align__(16) float4 se[128];
    __shared__ int ssrc[128];
    __shared__ float scm[NH];

    const int d = blockIdx.x, t = threadIdx.x, hd = t >> 5;
    const int beg = g_rowptr[d], end = g_rowptr[d + 1];
    const float4 ad = *(const float4*)(g_adst + d * NH);

    float4 acc = make_float4(0.f, 0.f, 0.f, 0.f);
    float m = __int_as_float(0xff800000);
    float s = 0.f;

    for (int c0 = beg; c0 < end; c0 += 128) {
        const int cnt = min(128, end - c0);
        __syncthreads();
        if (t < cnt) {
            const int sidx = g_csr[c0 + t];
            ssrc[t] = sidx;
            float4 a = *(const float4*)(g_asrc + sidx * NH);
            a.x += ad.x; a.y += ad.y; a.z += ad.z; a.w += ad.w;
            a.x = a.x > 0.f ? a.x : 0.2f * a.x;
            a.y = a.y > 0.f ? a.y : 0.2f * a.y;
            a.z = a.z > 0.f ? a.z : 0.2f * a.z;
            a.w = a.w > 0.f ? a.w : 0.2f * a.w;
            se[t] = a;
        }
        __syncthreads();

        float cm = m;
        for (int j = 0; j < cnt; j++) cm = fmaxf(cm, ((const float*)&se[j])[hd]);
        const float scale = expf(m - cm);
        acc.x *= scale; acc.y *= scale; acc.z *= scale; acc.w *= scale;
        s *= scale;
        m = cm;
        if ((t & 31) == 0) scm[hd] = cm;
        __syncthreads();

        for (int idx = t; idx < cnt * NH; idx += 128) {
            const int j = idx >> 2, h = idx & 3;
            ((float*)&se[j])[h] = expf(((const float*)&se[j])[h] - scm[h]);
        }
        __syncthreads();

        for (int j = 0; j < cnt; j++) {
            const float p = ((const float*)&se[j])[hd];
            s += p;
            const float4 hv = *(const float4*)(g_h + (size_t)ssrc[j] * HC + t * 4);
            acc.x += p * hv.x; acc.y += p * hv.y;
            acc.z += p * hv.z; acc.w += p * hv.w;
        }
    }

    const float inv = 1.f / (s + 1e-16f);
    const int c = t * 4;
    const float4 b4 = *(const float4*)(bias + c);
    float4 o = make_float4(acc.x * inv + b4.x, acc.y * inv + b4.y,
                           acc.z * inv + b4.z, acc.w * inv + b4.w);
    if (DO_ELU) {
        o.x = o.x > 0.f ? o.x : expm1f(o.x);
        o.y = o.y > 0.f ? o.y : expm1f(o.y);
        o.z = o.z > 0.f ? o.z : expm1f(o.z);
        o.w = o.w > 0.f ? o.w : expm1f(o.w);
    }
    *(float4*)(g_out + (size_t)d * HC + c) = o;
}

// ---------------- classifier tail -------------------------------------------
__global__ void logits_kernel(const float* __restrict__ Wc2,
                              const float* __restrict__ bc2,
                              float* __restrict__ out) {
    const int i = blockIdx.x * blockDim.x + threadIdx.x;
    if (i >= NN * 10) return;
    const int n = i / 10, j = i - n * 10;
    const float* z = g_z + (size_t)n * CH;
    float acc = bc2[j];
#pragma unroll 4
    for (int k = 0; k < CH; k++) acc += z[k] * Wc2[k * 10 + j];
    out[i] = acc;
}

// ---------------- launch ---------------------------------------------------
extern "C" void kernel_launch(void* const* d_in, const int* in_sizes, int n_in,
                              void* d_out, int out_size) {
    const float* x   = (const float*)d_in[0];
    const void*  ei  = d_in[1];
    const float* W1  = (const float*)d_in[2];
    const float* as1 = (const float*)d_in[3];
    const float* ad1 = (const float*)d_in[4];
    const float* b1  = (const float*)d_in[5];
    const float* W2  = (const float*)d_in[6];
    const float* as2 = (const float*)d_in[7];
    const float* ad2 = (const float*)d_in[8];
    const float* b2  = (const float*)d_in[9];
    const float* Wc1 = (const float*)d_in[10];
    const float* bc1 = (const float*)d_in[11];
    const float* Wc2 = (const float*)d_in[12];
    const float* bc2 = (const float*)d_in[13];
    float* out = (float*)d_out;

    static float* p_h = nullptr; static float* p_out = nullptr; static float* p_z = nullptr;
    static __nv_bfloat16 *p_ahi = nullptr, *p_alo = nullptr, *p_bhi = nullptr, *p_blo = nullptr;
    static const int SMEM_BYTES = 2 * STAGEB;       // 81920
    if (!p_h) {
        cudaGetSymbolAddress((void**)&p_h,   g_h);
        cudaGetSymbolAddress((void**)&p_out, g_out);
        cudaGetSymbolAddress((void**)&p_z,   g_z);
        cudaGetSymbolAddress((void**)&p_ahi, g_ahi);
        cudaGetSymbolAddress((void**)&p_alo, g_alo);
        cudaGetSymbolAddress((void**)&p_bhi, g_bhi);
        cudaGetSymbolAddress((void**)&p_blo, g_blo);
        cudaFuncSetAttribute(gemm_mma<0>, cudaFuncAttributeMaxDynamicSharedMemorySize, SMEM_BYTES);
        cudaFuncSetAttribute(gemm_mma<1>, cudaFuncAttributeMaxDynamicSharedMemorySize, SMEM_BYTES);
    }

    const int TPB = 256;
    const int alphaBlocks = (NN * NH * 32 + TPB - 1) / TPB;
    const int eBlocks     = (NEP + TPB - 1) / TPB;
    const int nodeBlocks  = (NN + TPB - 1) / TPB;
    const dim3 gG512(HC / 128, MPAD / 128);
    const dim3 gG128(CH / 128, MPAD / 128);

    // ---- CSR build ----
    probe_kernel<<<1, 1>>>(ei);
    zero_deg<<<nodeBlocks, TPB>>>();
    convert_kernel<<<eBlocks, TPB>>>(ei);
    scan1<<<NBLK, 256>>>();
    scan2<<<1, 256>>>();
    scan3<<<nodeBlocks, TPB>>>();
    csr_scatter<<<eBlocks, TPB>>>();

    // ---- layer 1 ----
    conv_w<<<(HC * KP1 + TPB - 1) / TPB, TPB>>>(W1, FIN, HC, KP1);
    conv_a<<<(MPAD * KP1 / 4 + TPB - 1) / TPB, TPB>>>(x, FIN, KP1);
    gemm_mma<0><<<gG512, TPB, SMEM_BYTES>>>(p_ahi, p_alo, p_bhi, p_blo, p_h, KP1, HC, nullptr);
    alpha_kernel<<<alphaBlocks, TPB>>>(as1, ad1);
    agg_kernel<1><<<NN, 128>>>(b1);

    // ---- layer 2 ----
    conv_w<<<(HC * KP2 + TPB - 1) / TPB, TPB>>>(W2, HC, HC, KP2);
    conv_a<<<(MPAD * KP2 / 4 + TPB - 1) / TPB, TPB>>>(p_out, HC, KP2);
    gemm_mma<0><<<gG512, TPB, SMEM_BYTES>>>(p_ahi, p_alo, p_bhi, p_blo, p_h, KP2, HC, nullptr);
    alpha_kernel<<<alphaBlocks, TPB>>>(as2, ad2);
    agg_kernel<0><<<NN, 128>>>(b2);

    // ---- classifier ----
    conv_w<<<(CH * KP2 + TPB - 1) / TPB, TPB>>>(Wc1, HC, CH, KP2);
    conv_a<<<(MPAD * KP2 / 4 + TPB - 1) / TPB, TPB>>>(p_out, HC, KP2);
    gemm_mma<1><<<gG128, TPB, SMEM_BYTES>>>(p_ahi, p_alo, p_bhi, p_blo, p_z, KP2, CH, bc1);
    logits_kernel<<<(NN * 10 + TPB - 1) / TPB, TPB>>>(Wc2, bc2, out);
}

// round 10
// speedup vs baseline: 1.1597x; 1.1597x over previous
#include <cuda_runtime.h>
#include <cuda_bf16.h>
#include <cstdint>

#define NN   50000
#define FIN  336
#define HC   512
#define NH   4
#define CH   128
#define NE   500000
#define NEP  (NE + NN)
#define MPAD 50048            // 391 * 128
#define KP1  384
#define KP2  512
#define NBLK 196              // ceil(NN/256)

// ---------------- scratch (device globals; no allocation allowed) ----------
__device__ __align__(16) float g_h[(size_t)NN * HC];
__device__ __align__(16) float g_z[(size_t)NN * CH];
__device__ __align__(16) float g_asrc[NN * NH];
__device__ __align__(16) float g_adst[NN * NH];
__device__ int g_src[NEP];
__device__ int g_dst[NEP];
__device__ int g_csr[NEP];
__device__ int g_deg[NN];
__device__ int g_scan[NN];
__device__ int g_bsum[256];
__device__ int g_rowptr[NN + 1];
__device__ int g_cursor[NN];
__device__ int g_is64;

__device__ __align__(16) __nv_bfloat16 g_ahi[(size_t)MPAD * KP2];
__device__ __align__(16) __nv_bfloat16 g_alo[(size_t)MPAD * KP2];
__device__ __align__(16) __nv_bfloat16 g_bhi[(size_t)HC * KP2];
__device__ __align__(16) __nv_bfloat16 g_blo[(size_t)HC * KP2];

// ---------------- helpers ---------------------------------------------------
__device__ __forceinline__ uint32_t smem_u32(const void* p) {
    uint32_t a;
    asm("{ .reg .u64 t; cvta.to.shared.u64 t, %1; cvt.u32.u64 %0, t; }" : "=r"(a) : "l"(p));
    return a;
}
__device__ __forceinline__ void cp16(uint32_t saddr, const void* g) {
    asm volatile("cp.async.cg.shared.global [%0], [%1], 16;" :: "r"(saddr), "l"(g));
}
#define CP_COMMIT()  asm volatile("cp.async.commit_group;" ::: "memory")
#define CP_WAIT(n)   asm volatile("cp.async.wait_group %0;" :: "n"(n) : "memory")

#define LDMX4(r0, r1, r2, r3, addr)                                            \
    asm volatile("ldmatrix.sync.aligned.m8n8.x4.shared.b16 {%0,%1,%2,%3}, [%4];" \
                 : "=r"(r0), "=r"(r1), "=r"(r2), "=r"(r3) : "r"(addr))

#define MMA16816(c, a, b0, b1)                                                 \
    asm volatile("mma.sync.aligned.m16n8k16.row.col.f32.bf16.bf16.f32 "        \
                 "{%0,%1,%2,%3}, {%4,%5,%6,%7}, {%8,%9}, {%0,%1,%2,%3};"       \
                 : "+f"((c)[0]), "+f"((c)[1]), "+f"((c)[2]), "+f"((c)[3])      \
                 : "r"((a)[0]), "r"((a)[1]), "r"((a)[2]), "r"((a)[3]),         \
                   "r"(b0), "r"(b1))

// ---------------- split-bf16 conversions ------------------------------------
__global__ void conv_a(const float* __restrict__ src, int Kin, int Kpad) {
    const int idx = blockIdx.x * blockDim.x + threadIdx.x;
    const int qpr = Kpad >> 2;
    if (idx >= MPAD * qpr) return;
    const int row = idx / qpr, col = (idx - row * qpr) << 2;
    float4 v = make_float4(0.f, 0.f, 0.f, 0.f);
    if (row < NN && col < Kin)
        v = *(const float4*)(src + (size_t)row * Kin + col);
    __nv_bfloat162 h01 = __floats2bfloat162_rn(v.x, v.y);
    __nv_bfloat162 h23 = __floats2bfloat162_rn(v.z, v.w);
    __nv_bfloat162 l01 = __floats2bfloat162_rn(v.x - __bfloat162float(h01.x),
                                               v.y - __bfloat162float(h01.y));
    __nv_bfloat162 l23 = __floats2bfloat162_rn(v.z - __bfloat162float(h23.x),
                                               v.w - __bfloat162float(h23.y));
    *(uint2*)(g_ahi + (size_t)idx * 4) = make_uint2(*(uint32_t*)&h01, *(uint32_t*)&h23);
    *(uint2*)(g_alo + (size_t)idx * 4) = make_uint2(*(uint32_t*)&l01, *(uint32_t*)&l23);
}

__global__ void conv_w(const float* __restrict__ W, int K, int N, int Kpad) {
    int idx = blockIdx.x * blockDim.x + threadIdx.x;
    if (idx >= N * Kpad) return;
    int n = idx / Kpad, k = idx - n * Kpad;
    float v = (k < K) ? W[(size_t)k * N + n] : 0.f;
    __nv_bfloat16 h = __float2bfloat16(v);
    g_bhi[idx] = h;
    g_blo[idx] = __float2bfloat16(v - __bfloat162float(h));
}

// ---------------- pipelined mma.sync GEMM: C = A[M,K] @ Bt[N,K]^T -----------
// CTA tile 128x64, BK=32, 8 warps (4M x 2N, warp 32x32), 2-stage cp.async,
// 2 CTAs/SM.
#define APITCH  40                      // halves per smem row (80 B)
#define A_PLANE (128 * APITCH * 2)      // 10240 B
#define B_PLANE (64 * APITCH * 2)       // 5120 B
#define STAGEB  (2 * A_PLANE + 2 * B_PLANE)  // 30720 B
template <int ACT>
__global__ void __launch_bounds__(256, 2) gemm_mma(
    const __nv_bfloat16* __restrict__ Ahi, const __nv_bfloat16* __restrict__ Alo,
    const __nv_bfloat16* __restrict__ Bhi, const __nv_bfloat16* __restrict__ Blo,
    float* __restrict__ C, int Kpad, int ldc, const float* __restrict__ bias) {
    extern __shared__ __align__(16) char smem[];
    const uint32_t sb0 = smem_u32(smem);

    const int tid = threadIdx.x, lane = tid & 31, wid = tid >> 5;
    const int wm = wid & 3, wn = wid >> 2;          // warp tile 32(M) x 32(N)
    const int n0 = blockIdx.x * 64, m0 = blockIdx.y * 128;

    const uint32_t aoff = ((wm * 32 + (lane & 15)) * APITCH + (lane >> 4) * 8) * 2;
    const uint32_t boff = ((wn * 32 + (lane & 7) + (lane >> 4) * 8) * APITCH
                          + ((lane >> 3) & 1) * 8) * 2;

    const int nk = Kpad >> 5;
    float acc[2][4][4] = {};

    auto load_stage = [&](int i, int s) {
        const int k0 = i << 5;
        const uint32_t sb = sb0 + s * STAGEB;
        const __nv_bfloat16* aH = Ahi + (size_t)m0 * Kpad + k0;
        const __nv_bfloat16* aL = Alo + (size_t)m0 * Kpad + k0;
        const __nv_bfloat16* bH = Bhi + (size_t)n0 * Kpad + k0;
        const __nv_bfloat16* bL = Blo + (size_t)n0 * Kpad + k0;
#pragma unroll
        for (int e = tid; e < 512; e += 256) {      // A: 128 rows x 4 chunks
            const int row = e >> 2, ch = e & 3;
            const uint32_t so = row * 80 + ch * 16;
            const size_t go = (size_t)row * Kpad + ch * 8;
            cp16(sb + so,           aH + go);
            cp16(sb + A_PLANE + so, aL + go);
        }
        {                                           // B: 64 rows x 4 chunks
            const int row = tid >> 2, ch = tid & 3;
            const uint32_t so = row * 80 + ch * 16;
            const size_t go = (size_t)row * Kpad + ch * 8;
            cp16(sb + 2 * A_PLANE + so,           bH + go);
            cp16(sb + 2 * A_PLANE + B_PLANE + so, bL + go);
        }
    };

    load_stage(0, 0);
    CP_COMMIT();

    for (int i = 0; i < nk; i++) {
        if (i + 1 < nk) { load_stage(i + 1, (i + 1) & 1); CP_COMMIT(); CP_WAIT(1); }
        else            { CP_WAIT(0); }
        __syncthreads();

        const uint32_t sb = sb0 + (i & 1) * STAGEB;
#pragma unroll
        for (int ks = 0; ks < 2; ks++) {
            const uint32_t kb = ks * 32;            // 16 halves
            uint32_t ah[2][4], al[2][4], bh[2][4], bl[2][4];
#pragma unroll
            for (int mi = 0; mi < 2; mi++) {
                const uint32_t ad = sb + aoff + mi * (16 * APITCH * 2) + kb;
                LDMX4(ah[mi][0], ah[mi][1], ah[mi][2], ah[mi][3], ad);
                LDMX4(al[mi][0], al[mi][1], al[mi][2], al[mi][3], ad + A_PLANE);
            }
#pragma unroll
            for (int g = 0; g < 2; g++) {
                const uint32_t bd = sb + 2 * A_PLANE + boff + g * (16 * APITCH * 2) + kb;
                LDMX4(bh[g][0], bh[g][1], bh[g][2], bh[g][3], bd);
                LDMX4(bl[g][0], bl[g][1], bl[g][2], bl[g][3], bd + B_PLANE);
            }
#pragma unroll
            for (int mi = 0; mi < 2; mi++)
#pragma unroll
                for (int ni = 0; ni < 4; ni++) {
                    const int g = ni >> 1, p = (ni & 1) * 2;
                    MMA16816(acc[mi][ni], ah[mi], bh[g][p], bh[g][p + 1]);
                    MMA16816(acc[mi][ni], ah[mi], bl[g][p], bl[g][p + 1]);
                    MMA16816(acc[mi][ni], al[mi], bh[g][p], bh[g][p + 1]);
                }
        }
        __syncthreads();
    }

#pragma unroll
    for (int mi = 0; mi < 2; mi++) {
        const int ra = m0 + wm * 32 + mi * 16 + (lane >> 2);
        const int rb = ra + 8;
#pragma unroll
        for (int ni = 0; ni < 4; ni++) {
            const int c = n0 + wn * 32 + ni * 8 + (lane & 3) * 2;
            float2 v0 = make_float2(acc[mi][ni][0], acc[mi][ni][1]);
            float2 v1 = make_float2(acc[mi][ni][2], acc[mi][ni][3]);
            if (ACT == 1) {
                const float b0 = bias[c], b1 = bias[c + 1];
                v0.x = fmaxf(v0.x + b0, 0.f); v0.y = fmaxf(v0.y + b1, 0.f);
                v1.x = fmaxf(v1.x + b0, 0.f); v1.y = fmaxf(v1.y + b1, 0.f);
            }
            if (ra < NN) *(float2*)(C + (size_t)ra * ldc + c) = v0;
            if (rb < NN) *(float2*)(C + (size_t)rb * ldc + c) = v1;
        }
    }
}

// ---------------- edge-index probe / convert / CSR build -------------------
__global__ void probe_kernel(const void* __restrict__ ei) {
    const long long* p = (const long long*)ei;
    int ok64 = 1;
    for (int i = 0; i < 64; i++) {
        long long v = p[i];
        if (v < 0 || v >= NN) ok64 = 0;
    }
    g_is64 = ok64;
}

__global__ void zero_deg() {
    const int i = blockIdx.x * blockDim.x + threadIdx.x;
    if (i < NN) g_deg[i] = 0;
}

__global__ void convert_kernel(const void* __restrict__ ei) {
    const int i = blockIdx.x * blockDim.x + threadIdx.x;
    if (i >= NEP) return;
    int s, d;
    if (i < NE) {
        if (g_is64) {
            const long long* p = (const long long*)ei;
            s = (int)p[i]; d = (int)p[NE + i];
        } else {
            const int* p = (const int*)ei;
            s = p[i]; d = p[NE + i];
        }
    } else {
        s = d = i - NE;
    }
    g_src[i] = s;
    g_dst[i] = d;
    atomicAdd(&g_deg[d], 1);
}

__global__ void scan1() {
    __shared__ int sd[256];
    const int b = blockIdx.x, t = threadIdx.x, i = b * 256 + t;
    int v = (i < NN) ? g_deg[i] : 0;
    sd[t] = v;
    __syncthreads();
#pragma unroll
    for (int o = 1; o < 256; o <<= 1) {
        int x = (t >= o) ? sd[t - o] : 0;
        __syncthreads();
        sd[t] += x;
        __syncthreads();
    }
    if (i < NN) g_scan[i] = sd[t];
    if (t == 255) g_bsum[b] = sd[255];
}

__global__ void scan2() {
    __shared__ int sd[256];
    const int t = threadIdx.x;
    sd[t] = (t < NBLK) ? g_bsum[t] : 0;
    __syncthreads();
#pragma unroll
    for (int o = 1; o < 256; o <<= 1) {
        int x = (t >= o) ? sd[t - o] : 0;
        __syncthreads();
        sd[t] += x;
        __syncthreads();
    }
    if (t < NBLK) g_bsum[t] = sd[t];
}

__global__ void scan3() {
    const int i = blockIdx.x * blockDim.x + threadIdx.x;
    if (i >= NN) return;
    const int b = i >> 8;
    const int incl = g_scan[i] + (b > 0 ? g_bsum[b - 1] : 0);
    g_rowptr[i + 1] = incl;
    g_cursor[i] = incl - g_deg[i];
    if (i == 0) g_rowptr[0] = 0;
}

__global__ void csr_scatter() {
    const int e = blockIdx.x * blockDim.x + threadIdx.x;
    if (e >= NEP) return;
    const int pos = atomicAdd(&g_cursor[g_dst[e]], 1);
    g_csr[pos] = g_src[e];
}

// ---------------- alpha coefficients ----------------------------------------
__global__ void alpha_kernel(const float* __restrict__ asrc,
                             const float* __restrict__ adst) {
    const int w = (blockIdx.x * blockDim.x + threadIdx.x) >> 5;
    const int lane = threadIdx.x & 31;
    if (w >= NN * NH) return;
    const int n = w >> 2, hd = w & 3;
    const float4 hv = *(const float4*)(g_h + (size_t)n * HC + hd * CH + lane * 4);
    const float4 as = *(const float4*)(asrc + hd * CH + lane * 4);
    const float4 ad = *(const float4*)(adst + hd * CH + lane * 4);
    float ss = hv.x * as.x + hv.y * as.y + hv.z * as.z + hv.w * as.w;
    float sd = hv.x * ad.x + hv.y * ad.y + hv.z * ad.z + hv.w * ad.w;
#pragma unroll
    for (int o = 16; o > 0; o >>= 1) {
        ss += __shfl_xor_sync(0xffffffffu, ss, o);
        sd += __shfl_xor_sync(0xffffffffu, sd, o);
    }
    if (lane == 0) { g_asrc[w] = ss; g_adst[w] = sd; }
}

// ---------------- fused gather aggregation (online softmax) ----------------
// one 128-thread block per dst node; thread t owns channels [4t, 4t+4).
// Epilogue writes the split-bf16 A planes for the NEXT GEMM directly.
template <int DO_ELU>
__global__ void __launch_bounds__(128) agg_kernel(const float* __restrict__ bias) {
    __shared__ __align__(16) float4 se[128];
    __shared__ int ssrc[128];
    __shared__ float scm[NH];

    const int d = blockIdx.x, t = threadIdx.x, hd = t >> 5;
    const int beg = g_rowptr[d], end = g_rowptr[d + 1];
    const float4 ad = *(const float4*)(g_adst + d * NH);

    float4 acc = make_float4(0.f, 0.f, 0.f, 0.f);
    float m = __int_as_float(0xff800000);
    float s = 0.f;

    for (int c0 = beg; c0 < end; c0 += 128) {
        const int cnt = min(128, end - c0);
        __syncthreads();
        if (t < cnt) {
            const int sidx = g_csr[c0 + t];
            ssrc[t] = sidx;
            float4 a = *(const float4*)(g_asrc + sidx * NH);
            a.x += ad.x; a.y += ad.y; a.z += ad.z; a.w += ad.w;
            a.x = a.x > 0.f ? a.x : 0.2f * a.x;
            a.y = a.y > 0.f ? a.y : 0.2f * a.y;
            a.z = a.z > 0.f ? a.z : 0.2f * a.z;
            a.w = a.w > 0.f ? a.w : 0.2f * a.w;
            se[t] = a;
        }
        __syncthreads();

        float cm = m;
        for (int j = 0; j < cnt; j++) cm = fmaxf(cm, ((const float*)&se[j])[hd]);
        const float scale = expf(m - cm);
        acc.x *= scale; acc.y *= scale; acc.z *= scale; acc.w *= scale;
        s *= scale;
        m = cm;
        if ((t & 31) == 0) scm[hd] = cm;
        __syncthreads();

        for (int idx = t; idx < cnt * NH; idx += 128) {
            const int j = idx >> 2, h = idx & 3;
            ((float*)&se[j])[h] = expf(((const float*)&se[j])[h] - scm[h]);
        }
        __syncthreads();

        for (int j = 0; j < cnt; j++) {
            const float p = ((const float*)&se[j])[hd];
            s += p;
            const float4 hv = *(const float4*)(g_h + (size_t)ssrc[j] * HC + t * 4);
            acc.x += p * hv.x; acc.y += p * hv.y;
            acc.z += p * hv.z; acc.w += p * hv.w;
        }
    }

    const float inv = 1.f / (s + 1e-16f);
    const int c = t * 4;
    const float4 b4 = *(const float4*)(bias + c);
    float4 o = make_float4(acc.x * inv + b4.x, acc.y * inv + b4.y,
                           acc.z * inv + b4.z, acc.w * inv + b4.w);
    if (DO_ELU) {
        o.x = o.x > 0.f ? o.x : expm1f(o.x);
        o.y = o.y > 0.f ? o.y : expm1f(o.y);
        o.z = o.z > 0.f ? o.z : expm1f(o.z);
        o.w = o.w > 0.f ? o.w : expm1f(o.w);
    }
    // split-bf16 write into A planes (pitch HC = KP2 = 512)
    __nv_bfloat162 h01 = __floats2bfloat162_rn(o.x, o.y);
    __nv_bfloat162 h23 = __floats2bfloat162_rn(o.z, o.w);
    __nv_bfloat162 l01 = __floats2bfloat162_rn(o.x - __bfloat162float(h01.x),
                                               o.y - __bfloat162float(h01.y));
    __nv_bfloat162 l23 = __floats2bfloat162_rn(o.z - __bfloat162float(h23.x),
                                               o.w - __bfloat162float(h23.y));
    const size_t base = (size_t)d * HC + c;
    *(uint2*)(g_ahi + base) = make_uint2(*(uint32_t*)&h01, *(uint32_t*)&h23);
    *(uint2*)(g_alo + base) = make_uint2(*(uint32_t*)&l01, *(uint32_t*)&l23);
}

// ---------------- classifier tail -------------------------------------------
__global__ void logits_kernel(const float* __restrict__ Wc2,
                              const float* __restrict__ bc2,
                              float* __restrict__ out) {
    const int i = blockIdx.x * blockDim.x + threadIdx.x;
    if (i >= NN * 10) return;
    const int n = i / 10, j = i - n * 10;
    const float* z = g_z + (size_t)n * CH;
    float acc = bc2[j];
#pragma unroll 4
    for (int k = 0; k < CH; k++) acc += z[k] * Wc2[k * 10 + j];
    out[i] = acc;
}

// ---------------- launch ---------------------------------------------------
extern "C" void kernel_launch(void* const* d_in, const int* in_sizes, int n_in,
                              void* d_out, int out_size) {
    const float* x   = (const float*)d_in[0];
    const void*  ei  = d_in[1];
    const float* W1  = (const float*)d_in[2];
    const float* as1 = (const float*)d_in[3];
    const float* ad1 = (const float*)d_in[4];
    const float* b1  = (const float*)d_in[5];
    const float* W2  = (const float*)d_in[6];
    const float* as2 = (const float*)d_in[7];
    const float* ad2 = (const float*)d_in[8];
    const float* b2  = (const float*)d_in[9];
    const float* Wc1 = (const float*)d_in[10];
    const float* bc1 = (const float*)d_in[11];
    const float* Wc2 = (const float*)d_in[12];
    const float* bc2 = (const float*)d_in[13];
    float* out = (float*)d_out;

    static float* p_h = nullptr; static float* p_z = nullptr;
    static __nv_bfloat16 *p_ahi = nullptr, *p_alo = nullptr, *p_bhi = nullptr, *p_blo = nullptr;
    static const int SMEM_BYTES = 2 * STAGEB;       // 61440
    if (!p_h) {
        cudaGetSymbolAddress((void**)&p_h,   g_h);
        cudaGetSymbolAddress((void**)&p_z,   g_z);
        cudaGetSymbolAddress((void**)&p_ahi, g_ahi);
        cudaGetSymbolAddress((void**)&p_alo, g_alo);
        cudaGetSymbolAddress((void**)&p_bhi, g_bhi);
        cudaGetSymbolAddress((void**)&p_blo, g_blo);
        cudaFuncSetAttribute(gemm_mma<0>, cudaFuncAttributeMaxDynamicSharedMemorySize, SMEM_BYTES);
        cudaFuncSetAttribute(gemm_mma<1>, cudaFuncAttributeMaxDynamicSharedMemorySize, SMEM_BYTES);
    }

    const int TPB = 256;
    const int alphaBlocks = (NN * NH * 32 + TPB - 1) / TPB;
    const int eBlocks     = (NEP + TPB - 1) / TPB;
    const int nodeBlocks  = (NN + TPB - 1) / TPB;
    const dim3 gG512(HC / 64, MPAD / 128);
    const dim3 gG128(CH / 64, MPAD / 128);

    // ---- CSR build ----
    probe_kernel<<<1, 1>>>(ei);
    zero_deg<<<nodeBlocks, TPB>>>();
    convert_kernel<<<eBlocks, TPB>>>(ei);
    scan1<<<NBLK, 256>>>();
    scan2<<<1, 256>>>();
    scan3<<<nodeBlocks, TPB>>>();
    csr_scatter<<<eBlocks, TPB>>>();

    // ---- layer 1 ----
    conv_w<<<(HC * KP1 + TPB - 1) / TPB, TPB>>>(W1, FIN, HC, KP1);
    conv_a<<<(MPAD * KP1 / 4 + TPB - 1) / TPB, TPB>>>(x, FIN, KP1);
    gemm_mma<0><<<gG512, TPB, SMEM_BYTES>>>(p_ahi, p_alo, p_bhi, p_blo, p_h, KP1, HC, nullptr);
    alpha_kernel<<<alphaBlocks, TPB>>>(as1, ad1);
    agg_kernel<1><<<NN, 128>>>(b1);                 // writes bf16 A planes

    // ---- layer 2 ----
    conv_w<<<(HC * KP2 + TPB - 1) / TPB, TPB>>>(W2, HC, HC, KP2);
    gemm_mma<0><<<gG512, TPB, SMEM_BYTES>>>(p_ahi, p_alo, p_bhi, p_blo, p_h, KP2, HC, nullptr);
    alpha_kernel<<<alphaBlocks, TPB>>>(as2, ad2);
    agg_kernel<0><<<NN, 128>>>(b2);                 // writes bf16 A planes

    // ---- classifier ----
    conv_w<<<(CH * KP2 + TPB - 1) / TPB, TPB>>>(Wc1, HC, CH, KP2);
    gemm_mma<1><<<gG128, TPB, SMEM_BYTES>>>(p_ahi, p_alo, p_bhi, p_blo, p_z, KP2, CH, bc1);
    logits_kernel<<<(NN * 10 + TPB - 1) / TPB, TPB>>>(Wc2, bc2, out);
}

// round 14
// speedup vs baseline: 1.2036x; 1.0378x over previous
#include <cuda_runtime.h>
#include <cuda_bf16.h>
#include <cstdint>

#define NN   50000
#define FIN  336
#define HC   512
#define NH   4
#define CH   128
#define NE   500000
#define NEP  (NE + NN)
#define MPAD 50048            // 391 * 128
#define KP1  352              // 11 slabs of 32 cover FIN=336
#define KP2  512
#define NBLK 196              // ceil(NN/256)

// ---------------- scratch (device globals; no allocation allowed) ----------
__device__ __align__(16) float g_h[(size_t)NN * HC];
__device__ __align__(16) float g_z[(size_t)NN * CH];
__device__ __align__(16) float g_asrc[NN * NH];
__device__ __align__(16) float g_adst[NN * NH];
__device__ int g_src[NEP];
__device__ int g_dst[NEP];
__device__ int g_csr[NEP];
__device__ int g_deg[NN];
__device__ int g_scan[NN];
__device__ int g_bsum[256];
__device__ int g_rowptr[NN + 1];
__device__ int g_cursor[NN];
__device__ int g_is64;

__device__ __align__(16) __nv_bfloat16 g_ahi[(size_t)MPAD * KP2];
__device__ __align__(16) __nv_bfloat16 g_alo[(size_t)MPAD * KP2];
__device__ __align__(16) __nv_bfloat16 g_bhi[(size_t)HC * KP2];
__device__ __align__(16) __nv_bfloat16 g_blo[(size_t)HC * KP2];

// ---------------- helpers ---------------------------------------------------
__device__ __forceinline__ uint32_t smem_u32(const void* p) {
    uint32_t a;
    asm("{ .reg .u64 t; cvta.to.shared.u64 t, %1; cvt.u32.u64 %0, t; }" : "=r"(a) : "l"(p));
    return a;
}
__device__ __forceinline__ void cp16(uint32_t saddr, const void* g) {
    asm volatile("cp.async.cg.shared.global [%0], [%1], 16;" :: "r"(saddr), "l"(g));
}
#define CP_COMMIT()  asm volatile("cp.async.commit_group;" ::: "memory")
#define CP_WAIT(n)   asm volatile("cp.async.wait_group %0;" :: "n"(n) : "memory")

#define LDMX4(r0, r1, r2, r3, addr)                                            \
    asm volatile("ldmatrix.sync.aligned.m8n8.x4.shared.b16 {%0,%1,%2,%3}, [%4];" \
                 : "=r"(r0), "=r"(r1), "=r"(r2), "=r"(r3) : "r"(addr))

#define MMA16816(c, a, b0, b1)                                                 \
    asm volatile("mma.sync.aligned.m16n8k16.row.col.f32.bf16.bf16.f32 "        \
                 "{%0,%1,%2,%3}, {%4,%5,%6,%7}, {%8,%9}, {%0,%1,%2,%3};"       \
                 : "+f"((c)[0]), "+f"((c)[1]), "+f"((c)[2]), "+f"((c)[3])      \
                 : "r"((a)[0]), "r"((a)[1]), "r"((a)[2]), "r"((a)[3]),         \
                   "r"(b0), "r"(b1))

// ---------------- split-bf16 conversions ------------------------------------
__global__ void conv_a(const float* __restrict__ src, int Kin, int Kpad) {
    const int idx = blockIdx.x * blockDim.x + threadIdx.x;
    const int qpr = Kpad >> 2;
    if (idx >= MPAD * qpr) return;
    const int row = idx / qpr, col = (idx - row * qpr) << 2;
    float4 v = make_float4(0.f, 0.f, 0.f, 0.f);
    if (row < NN && col < Kin)
        v = *(const float4*)(src + (size_t)row * Kin + col);
    __nv_bfloat162 h01 = __floats2bfloat162_rn(v.x, v.y);
    __nv_bfloat162 h23 = __floats2bfloat162_rn(v.z, v.w);
    __nv_bfloat162 l01 = __floats2bfloat162_rn(v.x - __bfloat162float(h01.x),
                                               v.y - __bfloat162float(h01.y));
    __nv_bfloat162 l23 = __floats2bfloat162_rn(v.z - __bfloat162float(h23.x),
                                               v.w - __bfloat162float(h23.y));
    *(uint2*)(g_ahi + (size_t)idx * 4) = make_uint2(*(uint32_t*)&h01, *(uint32_t*)&h23);
    *(uint2*)(g_alo + (size_t)idx * 4) = make_uint2(*(uint32_t*)&l01, *(uint32_t*)&l23);
}

__global__ void conv_w(const float* __restrict__ W, int K, int N, int Kpad) {
    int idx = blockIdx.x * blockDim.x + threadIdx.x;
    if (idx >= N * Kpad) return;
    int n = idx / Kpad, k = idx - n * Kpad;
    float v = (k < K) ? W[(size_t)k * N + n] : 0.f;
    __nv_bfloat16 h = __float2bfloat16(v);
    g_bhi[idx] = h;
    g_blo[idx] = __float2bfloat16(v - __bfloat162float(h));
}

// ---------------- pipelined mma.sync GEMM: C = A[M,K] @ Bt[N,K]^T -----------
// CTA tile 128x64, BK=32, 8 warps (4M x 2N, warp 32x32), 3-stage cp.async,
// one __syncthreads per slab, 2 CTAs/SM.
#define APITCH  40                      // halves per smem row (80 B)
#define A_PLANE (128 * APITCH * 2)      // 10240 B
#define B_PLANE (64 * APITCH * 2)       // 5120 B
#define STAGEB  (2 * A_PLANE + 2 * B_PLANE)  // 30720 B
#define NSTAGE  3
template <int ACT>
__global__ void __launch_bounds__(256, 2) gemm_mma(
    const __nv_bfloat16* __restrict__ Ahi, const __nv_bfloat16* __restrict__ Alo,
    const __nv_bfloat16* __restrict__ Bhi, const __nv_bfloat16* __restrict__ Blo,
    float* __restrict__ C, int Kpad, int ldc, const float* __restrict__ bias) {
    extern __shared__ __align__(16) char smem[];
    const uint32_t sb0 = smem_u32(smem);

    const int tid = threadIdx.x, lane = tid & 31, wid = tid >> 5;
    const int wm = wid & 3, wn = wid >> 2;          // warp tile 32(M) x 32(N)
    const int n0 = blockIdx.x * 64, m0 = blockIdx.y * 128;

    const uint32_t aoff = ((wm * 32 + (lane & 15)) * APITCH + (lane >> 4) * 8) * 2;
    const uint32_t boff = ((wn * 32 + (lane & 7) + (lane >> 4) * 8) * APITCH
                          + ((lane >> 3) & 1) * 8) * 2;

    const int nk = Kpad >> 5;
    float acc[2][4][4] = {};

    auto load_stage = [&](int i, int s) {
        const int k0 = i << 5;
        const uint32_t sb = sb0 + s * STAGEB;
        const __nv_bfloat16* aH = Ahi + (size_t)m0 * Kpad + k0;
        const __nv_bfloat16* aL = Alo + (size_t)m0 * Kpad + k0;
        const __nv_bfloat16* bH = Bhi + (size_t)n0 * Kpad + k0;
        const __nv_bfloat16* bL = Blo + (size_t)n0 * Kpad + k0;
#pragma unroll
        for (int e = tid; e < 512; e += 256) {      // A: 128 rows x 4 chunks
            const int row = e >> 2, ch = e & 3;
            const uint32_t so = row * 80 + ch * 16;
            const size_t go = (size_t)row * Kpad + ch * 8;
            cp16(sb + so,           aH + go);
            cp16(sb + A_PLANE + so, aL + go);
        }
        {                                           // B: 64 rows x 4 chunks
            const int row = tid >> 2, ch = tid & 3;
            const uint32_t so = row * 80 + ch * 16;
            const size_t go = (size_t)row * Kpad + ch * 8;
            cp16(sb + 2 * A_PLANE + so,           bH + go);
            cp16(sb + 2 * A_PLANE + B_PLANE + so, bL + go);
        }
    };

    load_stage(0, 0);
    CP_COMMIT();
    if (nk > 1) { load_stage(1, 1); CP_COMMIT(); }

    int s_cur = 0, s_nxt = 2;                       // (i)%3, (i+2)%3
    for (int i = 0; i < nk; i++) {
        if (i + 1 < nk) { CP_WAIT(1); } else { CP_WAIT(0); }
        __syncthreads();                            // stage i visible; buf (i+2)%3 free
        if (i + 2 < nk) { load_stage(i + 2, s_nxt); CP_COMMIT(); }

        const uint32_t sb = sb0 + s_cur * STAGEB;
#pragma unroll
        for (int ks = 0; ks < 2; ks++) {
            const uint32_t kb = ks * 32;            // 16 halves
            uint32_t ah[2][4], al[2][4], bh[2][4], bl[2][4];
#pragma unroll
            for (int mi = 0; mi < 2; mi++) {
                const uint32_t ad = sb + aoff + mi * (16 * APITCH * 2) + kb;
                LDMX4(ah[mi][0], ah[mi][1], ah[mi][2], ah[mi][3], ad);
                LDMX4(al[mi][0], al[mi][1], al[mi][2], al[mi][3], ad + A_PLANE);
            }
#pragma unroll
            for (int g = 0; g < 2; g++) {
                const uint32_t bd = sb + 2 * A_PLANE + boff + g * (16 * APITCH * 2) + kb;
                LDMX4(bh[g][0], bh[g][1], bh[g][2], bh[g][3], bd);
                LDMX4(bl[g][0], bl[g][1], bl[g][2], bl[g][3], bd + B_PLANE);
            }
#pragma unroll
            for (int mi = 0; mi < 2; mi++)
#pragma unroll
                for (int ni = 0; ni < 4; ni++) {
                    const int g = ni >> 1, p = (ni & 1) * 2;
                    MMA16816(acc[mi][ni], ah[mi], bh[g][p], bh[g][p + 1]);
                    MMA16816(acc[mi][ni], ah[mi], bl[g][p], bl[g][p + 1]);
                    MMA16816(acc[mi][ni], al[mi], bh[g][p], bh[g][p + 1]);
                }
        }
        s_cur = (s_cur == 2) ? 0 : s_cur + 1;
        s_nxt = (s_nxt == 2) ? 0 : s_nxt + 1;
    }

#pragma unroll
    for (int mi = 0; mi < 2; mi++) {
        const int ra = m0 + wm * 32 + mi * 16 + (lane >> 2);
        const int rb = ra + 8;
#pragma unroll
        for (int ni = 0; ni < 4; ni++) {
            const int c = n0 + wn * 32 + ni * 8 + (lane & 3) * 2;
            float2 v0 = make_float2(acc[mi][ni][0], acc[mi][ni][1]);
            float2 v1 = make_float2(acc[mi][ni][2], acc[mi][ni][3]);
            if (ACT == 1) {
                const float b0 = bias[c], b1 = bias[c + 1];
                v0.x = fmaxf(v0.x + b0, 0.f); v0.y = fmaxf(v0.y + b1, 0.f);
                v1.x = fmaxf(v1.x + b0, 0.f); v1.y = fmaxf(v1.y + b1, 0.f);
            }
            if (ra < NN) *(float2*)(C + (size_t)ra * ldc + c) = v0;
            if (rb < NN) *(float2*)(C + (size_t)rb * ldc + c) = v1;
        }
    }
}

// ---------------- edge-index probe / convert / CSR build -------------------
__global__ void probe_kernel(const void* __restrict__ ei) {
    const long long* p = (const long long*)ei;
    int ok64 = 1;
    for (int i = 0; i < 64; i++) {
        long long v = p[i];
        if (v < 0 || v >= NN) ok64 = 0;
    }
    g_is64 = ok64;
}

__global__ void zero_deg() {
    const int i = blockIdx.x * blockDim.x + threadIdx.x;
    if (i < NN) g_deg[i] = 0;
}

__global__ void convert_kernel(const void* __restrict__ ei) {
    const int i = blockIdx.x * blockDim.x + threadIdx.x;
    if (i >= NEP) return;
    int s, d;
    if (i < NE) {
        if (g_is64) {
            const long long* p = (const long long*)ei;
            s = (int)p[i]; d = (int)p[NE + i];
        } else {
            const int* p = (const int*)ei;
            s = p[i]; d = p[NE + i];
        }
    } else {
        s = d = i - NE;
    }
    g_src[i] = s;
    g_dst[i] = d;
    atomicAdd(&g_deg[d], 1);
}

__global__ void scan1() {
    __shared__ int sd[256];
    const int b = blockIdx.x, t = threadIdx.x, i = b * 256 + t;
    int v = (i < NN) ? g_deg[i] : 0;
    sd[t] = v;
    __syncthreads();
#pragma unroll
    for (int o = 1; o < 256; o <<= 1) {
        int x = (t >= o) ? sd[t - o] : 0;
        __syncthreads();
        sd[t] += x;
        __syncthreads();
    }
    if (i < NN) g_scan[i] = sd[t];
    if (t == 255) g_bsum[b] = sd[255];
}

__global__ void scan2() {
    __shared__ int sd[256];
    const int t = threadIdx.x;
    sd[t] = (t < NBLK) ? g_bsum[t] : 0;
    __syncthreads();
#pragma unroll
    for (int o = 1; o < 256; o <<= 1) {
        int x = (t >= o) ? sd[t - o] : 0;
        __syncthreads();
        sd[t] += x;
        __syncthreads();
    }
    if (t < NBLK) g_bsum[t] = sd[t];
}

__global__ void scan3() {
    const int i = blockIdx.x * blockDim.x + threadIdx.x;
    if (i >= NN) return;
    const int b = i >> 8;
    const int incl = g_scan[i] + (b > 0 ? g_bsum[b - 1] : 0);
    g_rowptr[i + 1] = incl;
    g_cursor[i] = incl - g_deg[i];
    if (i == 0) g_rowptr[0] = 0;
}

__global__ void csr_scatter() {
    const int e = blockIdx.x * blockDim.x + threadIdx.x;
    if (e >= NEP) return;
    const int pos = atomicAdd(&g_cursor[g_dst[e]], 1);
    g_csr[pos] = g_src[e];
}

// ---------------- alpha coefficients ----------------------------------------
__global__ void alpha_kernel(const float* __restrict__ asrc,
                             const float* __restrict__ adst) {
    const int w = (blockIdx.x * blockDim.x + threadIdx.x) >> 5;
    const int lane = threadIdx.x & 31;
    if (w >= NN * NH) return;
    const int n = w >> 2, hd = w & 3;
    const float4 hv = *(const float4*)(g_h + (size_t)n * HC + hd * CH + lane * 4);
    const float4 as = *(const float4*)(asrc + hd * CH + lane * 4);
    const float4 ad = *(const float4*)(adst + hd * CH + lane * 4);
    float ss = hv.x * as.x + hv.y * as.y + hv.z * as.z + hv.w * as.w;
    float sd = hv.x * ad.x + hv.y * ad.y + hv.z * ad.z + hv.w * ad.w;
#pragma unroll
    for (int o = 16; o > 0; o >>= 1) {
        ss += __shfl_xor_sync(0xffffffffu, ss, o);
        sd += __shfl_xor_sync(0xffffffffu, sd, o);
    }
    if (lane == 0) { g_asrc[w] = ss; g_adst[w] = sd; }
}

// ---------------- fused gather aggregation (online softmax) ----------------
template <int DO_ELU>
__global__ void __launch_bounds__(128) agg_kernel(const float* __restrict__ bias) {
    __shared__ __align__(16) float4 se[128];
    __shared__ int ssrc[128];
    __shared__ float scm[NH];

    const int d = blockIdx.x, t = threadIdx.x, hd = t >> 5;
    const int beg = g_rowptr[d], end = g_rowptr[d + 1];
    const float4 ad = *(const float4*)(g_adst + d * NH);

    float4 acc = make_float4(0.f, 0.f, 0.f, 0.f);
    float m = __int_as_float(0xff800000);
    float s = 0.f;

    for (int c0 = beg; c0 < end; c0 += 128) {
        const int cnt = min(128, end - c0);
        __syncthreads();
        if (t < cnt) {
            const int sidx = g_csr[c0 + t];
            ssrc[t] = sidx;
            float4 a = *(const float4*)(g_asrc + sidx * NH);
            a.x += ad.x; a.y += ad.y; a.z += ad.z; a.w += ad.w;
            a.x = a.x > 0.f ? a.x : 0.2f * a.x;
            a.y = a.y > 0.f ? a.y : 0.2f * a.y;
            a.z = a.z > 0.f ? a.z : 0.2f * a.z;
            a.w = a.w > 0.f ? a.w : 0.2f * a.w;
            se[t] = a;
        }
        __syncthreads();

        float cm = m;
        for (int j = 0; j < cnt; j++) cm = fmaxf(cm, ((const float*)&se[j])[hd]);
        const float scale = expf(m - cm);
        acc.x *= scale; acc.y *= scale; acc.z *= scale; acc.w *= scale;
        s *= scale;
        m = cm;
        if ((t & 31) == 0) scm[hd] = cm;
        __syncthreads();

        for (int idx = t; idx < cnt * NH; idx += 128) {
            const int j = idx >> 2, h = idx & 3;
            ((float*)&se[j])[h] = expf(((const float*)&se[j])[h] - scm[h]);
        }
        __syncthreads();

        for (int j = 0; j < cnt; j++) {
            const float p = ((const float*)&se[j])[hd];
            s += p;
            const float4 hv = *(const float4*)(g_h + (size_t)ssrc[j] * HC + t * 4);
            acc.x += p * hv.x; acc.y += p * hv.y;
            acc.z += p * hv.z; acc.w += p * hv.w;
        }
    }

    const float inv = 1.f / (s + 1e-16f);
    const int c = t * 4;
    const float4 b4 = *(const float4*)(bias + c);
    float4 o = make_float4(acc.x * inv + b4.x, acc.y * inv + b4.y,
                           acc.z * inv + b4.z, acc.w * inv + b4.w);
    if (DO_ELU) {
        o.x = o.x > 0.f ? o.x : expm1f(o.x);
        o.y = o.y > 0.f ? o.y : expm1f(o.y);
        o.z = o.z > 0.f ? o.z : expm1f(o.z);
        o.w = o.w > 0.f ? o.w : expm1f(o.w);
    }
    // split-bf16 write into A planes (pitch HC = KP2 = 512)
    __nv_bfloat162 h01 = __floats2bfloat162_rn(o.x, o.y);
    __nv_bfloat162 h23 = __floats2bfloat162_rn(o.z, o.w);
    __nv_bfloat162 l01 = __floats2bfloat162_rn(o.x - __bfloat162float(h01.x),
                                               o.y - __bfloat162float(h01.y));
    __nv_bfloat162 l23 = __floats2bfloat162_rn(o.z - __bfloat162float(h23.x),
                                               o.w - __bfloat162float(h23.y));
    const size_t base = (size_t)d * HC + c;
    *(uint2*)(g_ahi + base) = make_uint2(*(uint32_t*)&h01, *(uint32_t*)&h23);
    *(uint2*)(g_alo + base) = make_uint2(*(uint32_t*)&l01, *(uint32_t*)&l23);
}

// ---------------- classifier tail -------------------------------------------
__global__ void logits_kernel(const float* __restrict__ Wc2,
                              const float* __restrict__ bc2,
                              float* __restrict__ out) {
    const int i = blockIdx.x * blockDim.x + threadIdx.x;
    if (i >= NN * 10) return;
    const int n = i / 10, j = i - n * 10;
    const float* z = g_z + (size_t)n * CH;
    float acc = bc2[j];
#pragma unroll 4
    for (int k = 0; k < CH; k++) acc += z[k] * Wc2[k * 10 + j];
    out[i] = acc;
}

// ---------------- launch ---------------------------------------------------
extern "C" void kernel_launch(void* const* d_in, const int* in_sizes, int n_in,
                              void* d_out, int out_size) {
    const float* x   = (const float*)d_in[0];
    const void*  ei  = d_in[1];
    const float* W1  = (const float*)d_in[2];
    const float* as1 = (const float*)d_in[3];
    const float* ad1 = (const float*)d_in[4];
    const float* b1  = (const float*)d_in[5];
    const float* W2  = (const float*)d_in[6];
    const float* as2 = (const float*)d_in[7];
    const float* ad2 = (const float*)d_in[8];
    const float* b2  = (const float*)d_in[9];
    const float* Wc1 = (const float*)d_in[10];
    const float* bc1 = (const float*)d_in[11];
    const float* Wc2 = (const float*)d_in[12];
    const float* bc2 = (const float*)d_in[13];
    float* out = (float*)d_out;

    static float* p_h = nullptr; static float* p_z = nullptr;
    static __nv_bfloat16 *p_ahi = nullptr, *p_alo = nullptr, *p_bhi = nullptr, *p_blo = nullptr;
    static cudaStream_t s2;
    static cudaEvent_t evFork, evJoin;
    static const int SMEM_BYTES = NSTAGE * STAGEB;  // 92160
    if (!p_h) {
        cudaGetSymbolAddress((void**)&p_h,   g_h);
        cudaGetSymbolAddress((void**)&p_z,   g_z);
        cudaGetSymbolAddress((void**)&p_ahi, g_ahi);
        cudaGetSymbolAddress((void**)&p_alo, g_alo);
        cudaGetSymbolAddress((void**)&p_bhi, g_bhi);
        cudaGetSymbolAddress((void**)&p_blo, g_blo);
        cudaFuncSetAttribute(gemm_mma<0>, cudaFuncAttributeMaxDynamicSharedMemorySize, SMEM_BYTES);
        cudaFuncSetAttribute(gemm_mma<1>, cudaFuncAttributeMaxDynamicSharedMemorySize, SMEM_BYTES);
        cudaStreamCreateWithFlags(&s2, cudaStreamNonBlocking);
        cudaEventCreateWithFlags(&evFork, cudaEventDisableTiming);
        cudaEventCreateWithFlags(&evJoin, cudaEventDisableTiming);
    }

    const int TPB = 256;
    const int alphaBlocks = (NN * NH * 32 + TPB - 1) / TPB;
    const int eBlocks     = (NEP + TPB - 1) / TPB;
    const int nodeBlocks  = (NN + TPB - 1) / TPB;
    const dim3 gG512(HC / 64, MPAD / 128);
    const dim3 gG128(CH / 64, MPAD / 128);

    // ---- CSR build: forked onto s2, overlaps layer-1 conv/GEMM/alpha ----
    probe_kernel<<<1, 1>>>(ei);
    cudaEventRecord(evFork, 0);
    cudaStreamWaitEvent(s2, evFork, 0);
    zero_deg<<<nodeBlocks, TPB, 0, s2>>>();
    convert_kernel<<<eBlocks, TPB, 0, s2>>>(ei);
    scan1<<<NBLK, 256, 0, s2>>>();
    scan2<<<1, 256, 0, s2>>>();
    scan3<<<nodeBlocks, TPB, 0, s2>>>();
    csr_scatter<<<eBlocks, TPB, 0, s2>>>();
    cudaEventRecord(evJoin, s2);

    // ---- layer 1 (main stream, concurrent with CSR) ----
    conv_w<<<(HC * KP1 + TPB - 1) / TPB, TPB>>>(W1, FIN, HC, KP1);
    conv_a<<<(MPAD * KP1 / 4 + TPB - 1) / TPB, TPB>>>(x, FIN, KP1);
    gemm_mma<0><<<gG512, TPB, SMEM_BYTES>>>(p_ahi, p_alo, p_bhi, p_blo, p_h, KP1, HC, nullptr);
    alpha_kernel<<<alphaBlocks, TPB>>>(as1, ad1);
    cudaStreamWaitEvent(0, evJoin, 0);              // need CSR for agg
    agg_kernel<1><<<NN, 128>>>(b1);                 // writes bf16 A planes

    // ---- layer 2 ----
    conv_w<<<(HC * KP2 + TPB - 1) / TPB, TPB>>>(W2, HC, HC, KP2);
    gemm_mma<0><<<gG512, TPB, SMEM_BYTES>>>(p_ahi, p_alo, p_bhi, p_blo, p_h, KP2, HC, nullptr);
    alpha_kernel<<<alphaBlocks, TPB>>>(as2, ad2);
    agg_kernel<0><<<NN, 128>>>(b2);                 // writes bf16 A planes

    // ---- classifier ----
    conv_w<<<(CH * KP2 + TPB - 1) / TPB, TPB>>>(Wc1, HC, CH, KP2);
    gemm_mma<1><<<gG128, TPB, SMEM_BYTES>>>(p_ahi, p_alo, p_bhi, p_blo, p_z, KP2, CH, bc1);
    logits_kernel<<<(NN * 10 + TPB - 1) / TPB, TPB>>>(Wc2, bc2, out);
}

// round 15
// speedup vs baseline: 1.2337x; 1.0250x over previous
#include <cuda_runtime.h>
#include <cuda_bf16.h>
#include <cstdint>

#define NN   50000
#define FIN  336
#define HC   512
#define NH   4
#define CH   128
#define NE   500000
#define NEP  (NE + NN)
#define MPAD 50048            // 391 * 128
#define KP1  352              // 11 slabs of 32 cover FIN=336
#define KP2  512
#define NBLK 196              // ceil(NN/256)

// ---------------- scratch (device globals; no allocation allowed) ----------
__device__ __align__(16) float g_h[(size_t)NN * HC];
__device__ __align__(16) float g_z[(size_t)NN * CH];
__device__ __align__(16) float g_asrc[NN * NH];
__device__ __align__(16) float g_adst[NN * NH];
__device__ int g_src[NEP];
__device__ int g_dst[NEP];
__device__ int g_csr[NEP];
__device__ int g_deg[NN];
__device__ int g_scan[NN];
__device__ int g_bsum[256];
__device__ int g_rowptr[NN + 1];
__device__ int g_cursor[NN];
__device__ int g_is64;

__device__ __align__(16) __nv_bfloat16 g_ahi[(size_t)MPAD * KP2];
__device__ __align__(16) __nv_bfloat16 g_alo[(size_t)MPAD * KP2];
__device__ __align__(16) __nv_bfloat16 g_bhi[(size_t)HC * KP2];   // W1 planes
__device__ __align__(16) __nv_bfloat16 g_blo[(size_t)HC * KP2];
__device__ __align__(16) __nv_bfloat16 g_bhi2[(size_t)HC * KP2];  // W2 planes
__device__ __align__(16) __nv_bfloat16 g_blo2[(size_t)HC * KP2];
__device__ __align__(16) __nv_bfloat16 g_bhiC[(size_t)CH * KP2];  // Wc1 planes
__device__ __align__(16) __nv_bfloat16 g_bloC[(size_t)CH * KP2];

// ---------------- helpers ---------------------------------------------------
__device__ __forceinline__ uint32_t smem_u32(const void* p) {
    uint32_t a;
    asm("{ .reg .u64 t; cvta.to.shared.u64 t, %1; cvt.u32.u64 %0, t; }" : "=r"(a) : "l"(p));
    return a;
}
__device__ __forceinline__ void cp16(uint32_t saddr, const void* g) {
    asm volatile("cp.async.cg.shared.global [%0], [%1], 16;" :: "r"(saddr), "l"(g));
}
#define CP_COMMIT()  asm volatile("cp.async.commit_group;" ::: "memory")
#define CP_WAIT(n)   asm volatile("cp.async.wait_group %0;" :: "n"(n) : "memory")

#define LDMX4(r0, r1, r2, r3, addr)                                            \
    asm volatile("ldmatrix.sync.aligned.m8n8.x4.shared.b16 {%0,%1,%2,%3}, [%4];" \
                 : "=r"(r0), "=r"(r1), "=r"(r2), "=r"(r3) : "r"(addr))

#define MMA16816(c, a, b0, b1)                                                 \
    asm volatile("mma.sync.aligned.m16n8k16.row.col.f32.bf16.bf16.f32 "        \
                 "{%0,%1,%2,%3}, {%4,%5,%6,%7}, {%8,%9}, {%0,%1,%2,%3};"       \
                 : "+f"((c)[0]), "+f"((c)[1]), "+f"((c)[2]), "+f"((c)[3])      \
                 : "r"((a)[0]), "r"((a)[1]), "r"((a)[2]), "r"((a)[3]),         \
                   "r"(b0), "r"(b1))

// ---------------- split-bf16 conversions ------------------------------------
__global__ void conv_a(const float* __restrict__ src, int Kin, int Kpad) {
    const int idx = blockIdx.x * blockDim.x + threadIdx.x;
    const int qpr = Kpad >> 2;
    if (idx >= MPAD * qpr) return;
    const int row = idx / qpr, col = (idx - row * qpr) << 2;
    float4 v = make_float4(0.f, 0.f, 0.f, 0.f);
    if (row < NN && col < Kin)
        v = *(const float4*)(src + (size_t)row * Kin + col);
    __nv_bfloat162 h01 = __floats2bfloat162_rn(v.x, v.y);
    __nv_bfloat162 h23 = __floats2bfloat162_rn(v.z, v.w);
    __nv_bfloat162 l01 = __floats2bfloat162_rn(v.x - __bfloat162float(h01.x),
                                               v.y - __bfloat162float(h01.y));
    __nv_bfloat162 l23 = __floats2bfloat162_rn(v.z - __bfloat162float(h23.x),
                                               v.w - __bfloat162float(h23.y));
    *(uint2*)(g_ahi + (size_t)idx * 4) = make_uint2(*(uint32_t*)&h01, *(uint32_t*)&h23);
    *(uint2*)(g_alo + (size_t)idx * 4) = make_uint2(*(uint32_t*)&l01, *(uint32_t*)&l23);
}

__global__ void conv_w(const float* __restrict__ W, int K, int N, int Kpad,
                       __nv_bfloat16* __restrict__ bhi, __nv_bfloat16* __restrict__ blo) {
    int idx = blockIdx.x * blockDim.x + threadIdx.x;
    if (idx >= N * Kpad) return;
    int n = idx / Kpad, k = idx - n * Kpad;
    float v = (k < K) ? W[(size_t)k * N + n] : 0.f;
    __nv_bfloat16 h = __float2bfloat16(v);
    bhi[idx] = h;
    blo[idx] = __float2bfloat16(v - __bfloat162float(h));
}

__global__ void zero_alpha() {
    const int i = blockIdx.x * blockDim.x + threadIdx.x;
    if (i < NN * NH) { g_asrc[i] = 0.f; g_adst[i] = 0.f; }
}

// ---------------- pipelined mma.sync GEMM: C = A[M,K] @ Bt[N,K]^T -----------
// CTA tile 128x64, BK=32, 8 warps (4M x 2N, warp 32x32), 3-stage cp.async,
// one __syncthreads per slab, 2 CTAs/SM.
// ACT: 0 = plain store, 1 = bias+relu, 2 = plain store + fused alpha dots.
#define APITCH  40                      // halves per smem row (80 B)
#define A_PLANE (128 * APITCH * 2)      // 10240 B
#define B_PLANE (64 * APITCH * 2)       // 5120 B
#define STAGEB  (2 * A_PLANE + 2 * B_PLANE)  // 30720 B
#define NSTAGE  3
template <int ACT>
__global__ void __launch_bounds__(256, 2) gemm_mma(
    const __nv_bfloat16* __restrict__ Ahi, const __nv_bfloat16* __restrict__ Alo,
    const __nv_bfloat16* __restrict__ Bhi, const __nv_bfloat16* __restrict__ Blo,
    float* __restrict__ C, int Kpad, int ldc, const float* __restrict__ bias,
    const float* __restrict__ asrc, const float* __restrict__ adst) {
    extern __shared__ __align__(16) char smem[];
    const uint32_t sb0 = smem_u32(smem);

    const int tid = threadIdx.x, lane = tid & 31, wid = tid >> 5;
    const int wm = wid & 3, wn = wid >> 2;          // warp tile 32(M) x 32(N)
    const int n0 = blockIdx.x * 64, m0 = blockIdx.y * 128;

    const uint32_t aoff = ((wm * 32 + (lane & 15)) * APITCH + (lane >> 4) * 8) * 2;
    const uint32_t boff = ((wn * 32 + (lane & 7) + (lane >> 4) * 8) * APITCH
                          + ((lane >> 3) & 1) * 8) * 2;

    const int nk = Kpad >> 5;
    float acc[2][4][4] = {};

    auto load_stage = [&](int i, int s) {
        const int k0 = i << 5;
        const uint32_t sb = sb0 + s * STAGEB;
        const __nv_bfloat16* aH = Ahi + (size_t)m0 * Kpad + k0;
        const __nv_bfloat16* aL = Alo + (size_t)m0 * Kpad + k0;
        const __nv_bfloat16* bH = Bhi + (size_t)n0 * Kpad + k0;
        const __nv_bfloat16* bL = Blo + (size_t)n0 * Kpad + k0;
#pragma unroll
        for (int e = tid; e < 512; e += 256) {      // A: 128 rows x 4 chunks
            const int row = e >> 2, ch = e & 3;
            const uint32_t so = row * 80 + ch * 16;
            const size_t go = (size_t)row * Kpad + ch * 8;
            cp16(sb + so,           aH + go);
            cp16(sb + A_PLANE + so, aL + go);
        }
        {                                           // B: 64 rows x 4 chunks
            const int row = tid >> 2, ch = tid & 3;
            const uint32_t so = row * 80 + ch * 16;
            const size_t go = (size_t)row * Kpad + ch * 8;
            cp16(sb + 2 * A_PLANE + so,           bH + go);
            cp16(sb + 2 * A_PLANE + B_PLANE + so, bL + go);
        }
    };

    load_stage(0, 0);
    CP_COMMIT();
    if (nk > 1) { load_stage(1, 1); CP_COMMIT(); }

    int s_cur = 0, s_nxt = 2;                       // (i)%3, (i+2)%3
    for (int i = 0; i < nk; i++) {
        if (i + 1 < nk) { CP_WAIT(1); } else { CP_WAIT(0); }
        __syncthreads();                            // stage i visible; buf (i+2)%3 free
        if (i + 2 < nk) { load_stage(i + 2, s_nxt); CP_COMMIT(); }

        const uint32_t sb = sb0 + s_cur * STAGEB;
#pragma unroll
        for (int ks = 0; ks < 2; ks++) {
            const uint32_t kb = ks * 32;            // 16 halves
            uint32_t ah[2][4], al[2][4], bh[2][4], bl[2][4];
#pragma unroll
            for (int mi = 0; mi < 2; mi++) {
                const uint32_t ad = sb + aoff + mi * (16 * APITCH * 2) + kb;
                LDMX4(ah[mi][0], ah[mi][1], ah[mi][2], ah[mi][3], ad);
                LDMX4(al[mi][0], al[mi][1], al[mi][2], al[mi][3], ad + A_PLANE);
            }
#pragma unroll
            for (int g = 0; g < 2; g++) {
                const uint32_t bd = sb + 2 * A_PLANE + boff + g * (16 * APITCH * 2) + kb;
                LDMX4(bh[g][0], bh[g][1], bh[g][2], bh[g][3], bd);
                LDMX4(bl[g][0], bl[g][1], bl[g][2], bl[g][3], bd + B_PLANE);
            }
#pragma unroll
            for (int mi = 0; mi < 2; mi++)
#pragma unroll
                for (int ni = 0; ni < 4; ni++) {
                    const int g = ni >> 1, p = (ni & 1) * 2;
                    MMA16816(acc[mi][ni], ah[mi], bh[g][p], bh[g][p + 1]);
                    MMA16816(acc[mi][ni], ah[mi], bl[g][p], bl[g][p + 1]);
                    MMA16816(acc[mi][ni], al[mi], bh[g][p], bh[g][p + 1]);
                }
        }
        s_cur = (s_cur == 2) ? 0 : s_cur + 1;
        s_nxt = (s_nxt == 2) ? 0 : s_nxt + 1;
    }

    // ---- epilogue ----
    float csrc[8], cdst[8];
    if (ACT == 2) {
#pragma unroll
        for (int ni = 0; ni < 4; ni++)
#pragma unroll
            for (int q = 0; q < 2; q++) {
                const int col = n0 + wn * 32 + ni * 8 + (lane & 3) * 2 + q;
                csrc[ni * 2 + q] = asrc[col];
                cdst[ni * 2 + q] = adst[col];
            }
    }
    const int hd_out = (n0 + wn * 32) >> 7;         // head of this warp's 32-col span

#pragma unroll
    for (int mi = 0; mi < 2; mi++) {
        const int ra = m0 + wm * 32 + mi * 16 + (lane >> 2);
        const int rb = ra + 8;
#pragma unroll
        for (int ni = 0; ni < 4; ni++) {
            const int c = n0 + wn * 32 + ni * 8 + (lane & 3) * 2;
            float2 v0 = make_float2(acc[mi][ni][0], acc[mi][ni][1]);
            float2 v1 = make_float2(acc[mi][ni][2], acc[mi][ni][3]);
            if (ACT == 1) {
                const float b0 = bias[c], b1 = bias[c + 1];
                v0.x = fmaxf(v0.x + b0, 0.f); v0.y = fmaxf(v0.y + b1, 0.f);
                v1.x = fmaxf(v1.x + b0, 0.f); v1.y = fmaxf(v1.y + b1, 0.f);
            }
            if (ra < NN) *(float2*)(C + (size_t)ra * ldc + c) = v0;
            if (rb < NN) *(float2*)(C + (size_t)rb * ldc + c) = v1;
        }
        if (ACT == 2) {
#pragma unroll
            for (int v = 0; v < 2; v++) {
                const int r = (v == 0) ? ra : rb;
                float ss = 0.f, sd = 0.f;
#pragma unroll
                for (int ni = 0; ni < 4; ni++)
#pragma unroll
                    for (int q = 0; q < 2; q++) {
                        const float val = acc[mi][ni][v * 2 + q];
                        ss += val * csrc[ni * 2 + q];
                        sd += val * cdst[ni * 2 + q];
                    }
                ss += __shfl_xor_sync(0xffffffffu, ss, 1);
                ss += __shfl_xor_sync(0xffffffffu, ss, 2);
                sd += __shfl_xor_sync(0xffffffffu, sd, 1);
                sd += __shfl_xor_sync(0xffffffffu, sd, 2);
                if ((lane & 3) == 0 && r < NN) {
                    atomicAdd(&g_asrc[r * NH + hd_out], ss);
                    atomicAdd(&g_adst[r * NH + hd_out], sd);
                }
            }
        }
    }
}

// ---------------- edge-index probe / convert / CSR build -------------------
__global__ void probe_kernel(const void* __restrict__ ei) {
    const long long* p = (const long long*)ei;
    int ok64 = 1;
    for (int i = 0; i < 64; i++) {
        long long v = p[i];
        if (v < 0 || v >= NN) ok64 = 0;
    }
    g_is64 = ok64;
}

__global__ void zero_deg() {
    const int i = blockIdx.x * blockDim.x + threadIdx.x;
    if (i < NN) g_deg[i] = 0;
}

__global__ void convert_kernel(const void* __restrict__ ei) {
    const int i = blockIdx.x * blockDim.x + threadIdx.x;
    if (i >= NEP) return;
    int s, d;
    if (i < NE) {
        if (g_is64) {
            const long long* p = (const long long*)ei;
            s = (int)p[i]; d = (int)p[NE + i];
        } else {
            const int* p = (const int*)ei;
            s = p[i]; d = p[NE + i];
        }
    } else {
        s = d = i - NE;
    }
    g_src[i] = s;
    g_dst[i] = d;
    atomicAdd(&g_deg[d], 1);
}

__global__ void scan1() {
    __shared__ int sd[256];
    const int b = blockIdx.x, t = threadIdx.x, i = b * 256 + t;
    int v = (i < NN) ? g_deg[i] : 0;
    sd[t] = v;
    __syncthreads();
#pragma unroll
    for (int o = 1; o < 256; o <<= 1) {
        int x = (t >= o) ? sd[t - o] : 0;
        __syncthreads();
        sd[t] += x;
        __syncthreads();
    }
    if (i < NN) g_scan[i] = sd[t];
    if (t == 255) g_bsum[b] = sd[255];
}

__global__ void scan2() {
    __shared__ int sd[256];
    const int t = threadIdx.x;
    sd[t] = (t < NBLK) ? g_bsum[t] : 0;
    __syncthreads();
#pragma unroll
    for (int o = 1; o < 256; o <<= 1) {
        int x = (t >= o) ? sd[t - o] : 0;
        __syncthreads();
        sd[t] += x;
        __syncthreads();
    }
    if (t < NBLK) g_bsum[t] = sd[t];
}

__global__ void scan3() {
    const int i = blockIdx.x * blockDim.x + threadIdx.x;
    if (i >= NN) return;
    const int b = i >> 8;
    const int incl = g_scan[i] + (b > 0 ? g_bsum[b - 1] : 0);
    g_rowptr[i + 1] = incl;
    g_cursor[i] = incl - g_deg[i];
    if (i == 0) g_rowptr[0] = 0;
}

__global__ void csr_scatter() {
    const int e = blockIdx.x * blockDim.x + threadIdx.x;
    if (e >= NEP) return;
    const int pos = atomicAdd(&g_cursor[g_dst[e]], 1);
    g_csr[pos] = g_src[e];
}

// ---------------- fused gather aggregation (online softmax) ----------------
template <int DO_ELU>
__global__ void __launch_bounds__(128) agg_kernel(const float* __restrict__ bias) {
    __shared__ __align__(16) float4 se[128];
    __shared__ int ssrc[128];
    __shared__ float scm[NH];

    const int d = blockIdx.x, t = threadIdx.x, hd = t >> 5;
    const int beg = g_rowptr[d], end = g_rowptr[d + 1];
    const float4 ad = *(const float4*)(g_adst + d * NH);

    float4 acc = make_float4(0.f, 0.f, 0.f, 0.f);
    float m = __int_as_float(0xff800000);
    float s = 0.f;

    for (int c0 = beg; c0 < end; c0 += 128) {
        const int cnt = min(128, end - c0);
        __syncthreads();
        if (t < cnt) {
            const int sidx = g_csr[c0 + t];
            ssrc[t] = sidx;
            float4 a = *(const float4*)(g_asrc + sidx * NH);
            a.x += ad.x; a.y += ad.y; a.z += ad.z; a.w += ad.w;
            a.x = a.x > 0.f ? a.x : 0.2f * a.x;
            a.y = a.y > 0.f ? a.y : 0.2f * a.y;
            a.z = a.z > 0.f ? a.z : 0.2f * a.z;
            a.w = a.w > 0.f ? a.w : 0.2f * a.w;
            se[t] = a;
        }
        __syncthreads();

        float cm = m;
        for (int j = 0; j < cnt; j++) cm = fmaxf(cm, ((const float*)&se[j])[hd]);
        const float scale = expf(m - cm);
        acc.x *= scale; acc.y *= scale; acc.z *= scale; acc.w *= scale;
        s *= scale;
        m = cm;
        if ((t & 31) == 0) scm[hd] = cm;
        __syncthreads();

        for (int idx = t; idx < cnt * NH; idx += 128) {
            const int j = idx >> 2, h = idx & 3;
            ((float*)&se[j])[h] = expf(((const float*)&se[j])[h] - scm[h]);
        }
        __syncthreads();

        for (int j = 0; j < cnt; j++) {
            const float p = ((const float*)&se[j])[hd];
            s += p;
            const float4 hv = *(const float4*)(g_h + (size_t)ssrc[j] * HC + t * 4);
            acc.x += p * hv.x; acc.y += p * hv.y;
            acc.z += p * hv.z; acc.w += p * hv.w;
        }
    }

    const float inv = 1.f / (s + 1e-16f);
    const int c = t * 4;
    const float4 b4 = *(const float4*)(bias + c);
    float4 o = make_float4(acc.x * inv + b4.x, acc.y * inv + b4.y,
                           acc.z * inv + b4.z, acc.w * inv + b4.w);
    if (DO_ELU) {
        o.x = o.x > 0.f ? o.x : expm1f(o.x);
        o.y = o.y > 0.f ? o.y : expm1f(o.y);
        o.z = o.z > 0.f ? o.z : expm1f(o.z);
        o.w = o.w > 0.f ? o.w : expm1f(o.w);
    }
    // split-bf16 write into A planes (pitch HC = KP2 = 512)
    __nv_bfloat162 h01 = __floats2bfloat162_rn(o.x, o.y);
    __nv_bfloat162 h23 = __floats2bfloat162_rn(o.z, o.w);
    __nv_bfloat162 l01 = __floats2bfloat162_rn(o.x - __bfloat162float(h01.x),
                                               o.y - __bfloat162float(h01.y));
    __nv_bfloat162 l23 = __floats2bfloat162_rn(o.z - __bfloat162float(h23.x),
                                               o.w - __bfloat162float(h23.y));
    const size_t base = (size_t)d * HC + c;
    *(uint2*)(g_ahi + base) = make_uint2(*(uint32_t*)&h01, *(uint32_t*)&h23);
    *(uint2*)(g_alo + base) = make_uint2(*(uint32_t*)&l01, *(uint32_t*)&l23);
}

// ---------------- classifier tail -------------------------------------------
__global__ void logits_kernel(const float* __restrict__ Wc2,
                              const float* __restrict__ bc2,
                              float* __restrict__ out) {
    const int i = blockIdx.x * blockDim.x + threadIdx.x;
    if (i >= NN * 10) return;
    const int n = i / 10, j = i - n * 10;
    const float* z = g_z + (size_t)n * CH;
    float acc = bc2[j];
#pragma unroll 4
    for (int k = 0; k < CH; k++) acc += z[k] * Wc2[k * 10 + j];
    out[i] = acc;
}

// ---------------- launch ---------------------------------------------------
extern "C" void kernel_launch(void* const* d_in, const int* in_sizes, int n_in,
                              void* d_out, int out_size) {
    const float* x   = (const float*)d_in[0];
    const void*  ei  = d_in[1];
    const float* W1  = (const float*)d_in[2];
    const float* as1 = (const float*)d_in[3];
    const float* ad1 = (const float*)d_in[4];
    const float* b1  = (const float*)d_in[5];
    const float* W2  = (const float*)d_in[6];
    const float* as2 = (const float*)d_in[7];
    const float* ad2 = (const float*)d_in[8];
    const float* b2  = (const float*)d_in[9];
    const float* Wc1 = (const float*)d_in[10];
    const float* bc1 = (const float*)d_in[11];
    const float* Wc2 = (const float*)d_in[12];
    const float* bc2 = (const float*)d_in[13];
    float* out = (float*)d_out;

    static float* p_h = nullptr; static float* p_z = nullptr;
    static __nv_bfloat16 *p_ahi = nullptr, *p_alo = nullptr;
    static __nv_bfloat16 *p_bhi = nullptr, *p_blo = nullptr;
    static __nv_bfloat16 *p_bhi2 = nullptr, *p_blo2 = nullptr;
    static __nv_bfloat16 *p_bhiC = nullptr, *p_bloC = nullptr;
    static cudaStream_t s2;
    static cudaEvent_t evFork, evJoin, evW;
    static const int SMEM_BYTES = NSTAGE * STAGEB;  // 92160
    if (!p_h) {
        cudaGetSymbolAddress((void**)&p_h,    g_h);
        cudaGetSymbolAddress((void**)&p_z,    g_z);
        cudaGetSymbolAddress((void**)&p_ahi,  g_ahi);
        cudaGetSymbolAddress((void**)&p_alo,  g_alo);
        cudaGetSymbolAddress((void**)&p_bhi,  g_bhi);
        cudaGetSymbolAddress((void**)&p_blo,  g_blo);
        cudaGetSymbolAddress((void**)&p_bhi2, g_bhi2);
        cudaGetSymbolAddress((void**)&p_blo2, g_blo2);
        cudaGetSymbolAddress((void**)&p_bhiC, g_bhiC);
        cudaGetSymbolAddress((void**)&p_bloC, g_bloC);
        cudaFuncSetAttribute(gemm_mma<0>, cudaFuncAttributeMaxDynamicSharedMemorySize, SMEM_BYTES);
        cudaFuncSetAttribute(gemm_mma<1>, cudaFuncAttributeMaxDynamicSharedMemorySize, SMEM_BYTES);
        cudaFuncSetAttribute(gemm_mma<2>, cudaFuncAttributeMaxDynamicSharedMemorySize, SMEM_BYTES);
        cudaStreamCreateWithFlags(&s2, cudaStreamNonBlocking);
        cudaEventCreateWithFlags(&evFork, cudaEventDisableTiming);
        cudaEventCreateWithFlags(&evJoin, cudaEventDisableTiming);
        cudaEventCreateWithFlags(&evW,    cudaEventDisableTiming);
    }

    const int TPB = 256;
    const int eBlocks    = (NEP + TPB - 1) / TPB;
    const int nodeBlocks = (NN + TPB - 1) / TPB;
    const int zaBlocks   = (NN * NH + TPB - 1) / TPB;
    const dim3 gG512(HC / 64, MPAD / 128);
    const dim3 gG128(CH / 64, MPAD / 128);

    // ---- side stream: CSR build + W2/Wc1 conversions (overlap layer 1) ----
    probe_kernel<<<1, 1>>>(ei);
    cudaEventRecord(evFork, 0);
    cudaStreamWaitEvent(s2, evFork, 0);
    zero_deg<<<nodeBlocks, TPB, 0, s2>>>();
    convert_kernel<<<eBlocks, TPB, 0, s2>>>(ei);
    scan1<<<NBLK, 256, 0, s2>>>();
    scan2<<<1, 256, 0, s2>>>();
    scan3<<<nodeBlocks, TPB, 0, s2>>>();
    csr_scatter<<<eBlocks, TPB, 0, s2>>>();
    cudaEventRecord(evJoin, s2);
    conv_w<<<(HC * KP2 + TPB - 1) / TPB, TPB, 0, s2>>>(W2, HC, HC, KP2, p_bhi2, p_blo2);
    conv_w<<<(CH * KP2 + TPB - 1) / TPB, TPB, 0, s2>>>(Wc1, HC, CH, KP2, p_bhiC, p_bloC);
    cudaEventRecord(evW, s2);

    // ---- layer 1 (main stream, concurrent with side stream) ----
    conv_w<<<(HC * KP1 + TPB - 1) / TPB, TPB>>>(W1, FIN, HC, KP1, p_bhi, p_blo);
    conv_a<<<(MPAD * KP1 / 4 + TPB - 1) / TPB, TPB>>>(x, FIN, KP1);
    zero_alpha<<<zaBlocks, TPB>>>();
    gemm_mma<2><<<gG512, TPB, SMEM_BYTES>>>(p_ahi, p_alo, p_bhi, p_blo, p_h, KP1, HC,
                                            nullptr, as1, ad1);
    cudaStreamWaitEvent(0, evJoin, 0);              // need CSR for agg
    agg_kernel<1><<<NN, 128>>>(b1);                 // writes bf16 A planes

    // ---- layer 2 ----
    zero_alpha<<<zaBlocks, TPB>>>();
    cudaStreamWaitEvent(0, evW, 0);                 // need W2/Wc1 planes
    gemm_mma<2><<<gG512, TPB, SMEM_BYTES>>>(p_ahi, p_alo, p_bhi2, p_blo2, p_h, KP2, HC,
                                            nullptr, as2, ad2);
    agg_kernel<0><<<NN, 128>>>(b2);                 // writes bf16 A planes

    // ---- classifier ----
    gemm_mma<1><<<gG128, TPB, SMEM_BYTES>>>(p_ahi, p_alo, p_bhiC, p_bloC, p_z, KP2, CH,
                                            bc1, nullptr, nullptr);
    logits_kernel<<<(NN * 10 + TPB - 1) / TPB, TPB>>>(Wc2, bc2, out);
}